// round 7
// baseline (speedup 1.0000x reference)
#include <cuda_runtime.h>
#include <cuda_bf16.h>
#include <math.h>
#include <stdint.h>

#define B_SZ  4096
#define D_IN  1024
#define HID   2048
#define NSEG  10
#define D_CTX 1024
#define D_OUT 1024
#define KWIN  102

// ---------------- scratch (device globals, allocation-free) ----------------
__device__ float g_dend[(size_t)B_SZ * HID * NSEG]; // 4096 x 20480  (~335 MB)
__device__ float g_y[(size_t)B_SZ * HID];           // pre-gate linear output
__device__ float g_h[(size_t)B_SZ * HID];           // gated + k-winners output

// ---------------- bf16 3-way split (RN, exact residuals) --------------------
__device__ __forceinline__ void split3(float a, float& h, float& m, float& l) {
    h = __bfloat162float(__float2bfloat16(a));
    float r1 = a - h;                       // exact (Sterbenz)
    m = __bfloat162float(__float2bfloat16(r1));
    float r2 = r1 - m;                      // exact
    l = __bfloat162float(__float2bfloat16(r2));
}

// ---------------- cuBLAS-13 BF16x9 emulation GEMM: C = A @ W^T (+bias) ------
// Model: per k-tile of 16 (one HMMA.k16), nine bf16 slice-MMAs (a-slice major:
// hh,hm,hl,mh,mm,ml,lh,lm,ll), each an exact 16-term dot (products of bf16
// values are exact in fp32/fp64; fp64 sum is exact here) folded into the fp32
// accumulator with a single rounding per MMA — wide-internal-accumulator
// tensor-core semantics. This reproduces the fp32-emulation numerics cuBLAS 13
// applies by default to SGEMM on sm_103.
#define TM 64
#define TN 64
#define TK 16

__global__ __launch_bounds__(256)
void gemm_bf16x9(const float* __restrict__ A, const float* __restrict__ W,
                 const float* __restrict__ bias, float* __restrict__ C,
                 int M, int N, int K)
{
    __shared__ float Ah[TK][TM], Am[TK][TM], Al[TK][TM];
    __shared__ float Bh[TK][TN], Bm[TK][TN], Bl[TK][TN];

    const int tid = threadIdx.x;
    const int bm  = blockIdx.y * TM;
    const int bn  = blockIdx.x * TN;
    const int ty  = tid >> 4;   // 0..15 -> rows ty + 16*i (i<4)
    const int tx  = tid & 15;   // 0..15 -> cols tx + 16*j (j<4)

    const int srow = tid >> 2;        // 0..63
    const int scg  = (tid & 3) * 4;   // 0,4,8,12

    float acc[4][4];
#pragma unroll
    for (int i = 0; i < 4; i++)
#pragma unroll
        for (int j = 0; j < 4; j++) acc[i][j] = 0.f;

    for (int k0 = 0; k0 < K; k0 += TK) {
        {
            float4 va = *(const float4*)(A + (size_t)(bm + srow) * K + k0 + scg);
            float h, m, l;
            split3(va.x, h, m, l); Ah[scg+0][srow]=h; Am[scg+0][srow]=m; Al[scg+0][srow]=l;
            split3(va.y, h, m, l); Ah[scg+1][srow]=h; Am[scg+1][srow]=m; Al[scg+1][srow]=l;
            split3(va.z, h, m, l); Ah[scg+2][srow]=h; Am[scg+2][srow]=m; Al[scg+2][srow]=l;
            split3(va.w, h, m, l); Ah[scg+3][srow]=h; Am[scg+3][srow]=m; Al[scg+3][srow]=l;
            float4 vb = *(const float4*)(W + (size_t)(bn + srow) * K + k0 + scg);
            split3(vb.x, h, m, l); Bh[scg+0][srow]=h; Bm[scg+0][srow]=m; Bl[scg+0][srow]=l;
            split3(vb.y, h, m, l); Bh[scg+1][srow]=h; Bm[scg+1][srow]=m; Bl[scg+1][srow]=l;
            split3(vb.z, h, m, l); Bh[scg+2][srow]=h; Bm[scg+2][srow]=m; Bl[scg+2][srow]=l;
            split3(vb.w, h, m, l); Bh[scg+3][srow]=h; Bm[scg+3][srow]=m; Bl[scg+3][srow]=l;
        }
        __syncthreads();

        // 9 slice-MMAs per k16 tile, a-slice-major order
#pragma unroll
        for (int p = 0; p < 9; p++) {
            const int pa = p / 3, pb = p % 3;
            const float (*Ap)[TM] = (pa == 0) ? Ah : (pa == 1 ? Am : Al);
            const float (*Bp)[TN] = (pb == 0) ? Bh : (pb == 1 ? Bm : Bl);

            double dacc[4][4];
#pragma unroll
            for (int i = 0; i < 4; i++)
#pragma unroll
                for (int j = 0; j < 4; j++) dacc[i][j] = 0.0;

#pragma unroll
            for (int k = 0; k < TK; k++) {
                double ra[4], rb[4];
#pragma unroll
                for (int i = 0; i < 4; i++) ra[i] = (double)Ap[k][ty + 16 * i];
#pragma unroll
                for (int j = 0; j < 4; j++) rb[j] = (double)Bp[k][tx + 16 * j];
#pragma unroll
                for (int i = 0; i < 4; i++)
#pragma unroll
                    for (int j = 0; j < 4; j++)
                        dacc[i][j] = fma(ra[i], rb[j], dacc[i][j]);
            }
            // single fp32 rounding per MMA (wide internal accumulator model)
#pragma unroll
            for (int i = 0; i < 4; i++)
#pragma unroll
                for (int j = 0; j < 4; j++)
                    acc[i][j] = (float)((double)acc[i][j] + dacc[i][j]);
        }
        __syncthreads();
    }

    const bool has_bias = (bias != nullptr);
#pragma unroll
    for (int i = 0; i < 4; i++) {
        int m = bm + ty + 16 * i;
#pragma unroll
        for (int j = 0; j < 4; j++) {
            int n = bn + tx + 16 * j;
            float cv = acc[i][j];
            if (has_bias) cv = __fadd_rn(cv, bias[n]);
            C[(size_t)m * N + n] = cv;
        }
    }
}

// ---------------- gating (abs-max segment, sigmoid) + exact k-winners -------
__global__ __launch_bounds__(256)
void gate_topk(const float* __restrict__ y, const float* __restrict__ dend,
               float* __restrict__ out)
{
    __shared__ float     vals[HID];
    __shared__ unsigned  keys[HID];
    __shared__ int       hist[256];
    __shared__ unsigned  s_prefix;
    __shared__ int       s_remaining;

    const int b   = blockIdx.x;
    const int tid = threadIdx.x;
    const float* drow = dend + (size_t)b * HID * NSEG;
    const float* yrow = y    + (size_t)b * HID;

    for (int h = tid; h < HID; h += 256) {
        float best = 0.f, bestabs = -1.f;
#pragma unroll
        for (int s = 0; s < NSEG; s++) {
            float v = drow[h * NSEG + s];
            float a = fabsf(v);
            if (a > bestabs) { bestabs = a; best = v; }  // first-occurrence argmax
        }
        float g = yrow[h] * (1.f / (1.f + expf(-best)));
        vals[h] = g;
        unsigned u = __float_as_uint(g);
        keys[h] = (u & 0x80000000u) ? ~u : (u | 0x80000000u); // order-preserving
    }
    if (tid == 0) { s_prefix = 0u; s_remaining = KWIN; }
    __syncthreads();

    for (int d = 3; d >= 0; d--) {
        hist[tid] = 0;
        __syncthreads();
        const unsigned pmask = (d == 3) ? 0u : (0xFFFFFFFFu << ((d + 1) * 8));
        const unsigned pref  = s_prefix;
        const int shift = d * 8;
        for (int h = tid; h < HID; h += 256) {
            unsigned kk = keys[h];
            if ((kk & pmask) == pref)
                atomicAdd(&hist[(kk >> shift) & 0xFF], 1);
        }
        __syncthreads();
        if (tid == 0) {
            int rem = s_remaining, cum = 0, bkt = 255;
            for (; bkt > 0; bkt--) {
                int c = hist[bkt];
                if (cum + c >= rem) break;
                cum += c;
            }
            s_remaining = rem - cum;
            s_prefix    = pref | ((unsigned)bkt << shift);
        }
        __syncthreads();
    }

    const unsigned kth = s_prefix;
    for (int h = tid; h < HID; h += 256)
        out[(size_t)b * HID + h] = (keys[h] >= kth) ? vals[h] : 0.f;
}

// ---------------- launch -----------------------------------------------------
extern "C" void kernel_launch(void* const* d_in, const int* in_sizes, int n_in,
                              void* d_out, int out_size)
{
    (void)in_sizes; (void)n_in; (void)out_size;
    const float* x     = (const float*)d_in[0];
    const float* ctx   = (const float*)d_in[1];
    const float* w1    = (const float*)d_in[2];
    const float* b1    = (const float*)d_in[3];
    const float* seg1  = (const float*)d_in[4];
    const float* w2    = (const float*)d_in[5];
    const float* b2    = (const float*)d_in[6];
    const float* seg2  = (const float*)d_in[7];
    const float* w_out = (const float*)d_in[8];
    const float* b_out = (const float*)d_in[9];
    float* out = (float*)d_out;

    float *dendp = nullptr, *yp = nullptr, *hp = nullptr;
    cudaGetSymbolAddress((void**)&dendp, g_dend);
    cudaGetSymbolAddress((void**)&yp,    g_y);
    cudaGetSymbolAddress((void**)&hp,    g_h);

    dim3 blk(256);

    // layer 1: linear + dendrites + gate/top-k
    gemm_bf16x9<<<dim3(HID / TN, B_SZ / TM), blk>>>(x,   w1,   b1,      yp,    B_SZ, HID,        D_IN);
    gemm_bf16x9<<<dim3(HID * NSEG / TN, B_SZ / TM), blk>>>(ctx, seg1, nullptr, dendp, B_SZ, HID * NSEG, D_CTX);
    gate_topk<<<B_SZ, 256>>>(yp, dendp, hp);

    // layer 2
    gemm_bf16x9<<<dim3(HID / TN, B_SZ / TM), blk>>>(hp,  w2,   b2,      yp,    B_SZ, HID,        HID);
    gemm_bf16x9<<<dim3(HID * NSEG / TN, B_SZ / TM), blk>>>(ctx, seg2, nullptr, dendp, B_SZ, HID * NSEG, D_CTX);
    gate_topk<<<B_SZ, 256>>>(yp, dendp, hp);

    // output projection
    gemm_bf16x9<<<dim3(D_OUT / TN, B_SZ / TM), blk>>>(hp, w_out, b_out, out, B_SZ, D_OUT, HID);
}

// round 10
// speedup vs baseline: 348.4563x; 348.4563x over previous
#include <cuda_runtime.h>
#include <cuda_bf16.h>
#include <math.h>
#include <stdint.h>

#define B_SZ  4096
#define D_IN  1024
#define HID   2048
#define NSEG  10
#define D_CTX 1024
#define D_OUT 1024
#define KWIN  102

// ---------------- scratch (device globals, allocation-free) ----------------
__device__ float g_dend[(size_t)B_SZ * HID * NSEG]; // 4096 x 20480  (~335 MB)
__device__ float g_y[(size_t)B_SZ * HID];           // pre-gate linear output

// bf16 hi/mid/lo splits of every GEMM operand (exact 3-way decomposition)
__device__ __nv_bfloat16 g_xs [3][(size_t)B_SZ * D_IN];
__device__ __nv_bfloat16 g_cs [3][(size_t)B_SZ * D_CTX];
__device__ __nv_bfloat16 g_w1s[3][(size_t)HID * D_IN];
__device__ __nv_bfloat16 g_s1s[3][(size_t)HID * NSEG * D_CTX];
__device__ __nv_bfloat16 g_w2s[3][(size_t)HID * HID];
__device__ __nv_bfloat16 g_s2s[3][(size_t)HID * NSEG * D_CTX];
__device__ __nv_bfloat16 g_wos[3][(size_t)D_OUT * HID];
__device__ __nv_bfloat16 g_hs [3][(size_t)B_SZ * HID];

// ---------------- bf16 3-way split ------------------------------------------
__global__ void split_kernel(const float* __restrict__ src,
                             __nv_bfloat16* __restrict__ hh,
                             __nv_bfloat16* __restrict__ mm,
                             __nv_bfloat16* __restrict__ ll, size_t n)
{
    for (size_t i = (size_t)blockIdx.x * blockDim.x + threadIdx.x; i < n;
         i += (size_t)gridDim.x * blockDim.x) {
        float a = src[i];
        __nv_bfloat16 hb = __float2bfloat16(a);
        float hf = __bfloat162float(hb);
        float r1 = a - hf;                         // exact
        __nv_bfloat16 mb = __float2bfloat16(r1);
        float mf = __bfloat162float(mb);
        float r2 = r1 - mf;                        // exact
        hh[i] = hb; mm[i] = mb; ll[i] = __float2bfloat16(r2);
    }
}

// ---------------- bf16 HMMA x9 GEMM: C = A @ B^T (+bias) --------------------
// A,B pre-split hi/mid/lo bf16, [rows, K] row-major. CTA tile 128x128,
// 8 warps of 64x32. Per k16: 9 slice-MMAs (a-slice-major: hh,hm,hl,mh,...),
// each issued with C=0 (so HMMA's internal reduced-precision accumulate never
// touches the large running value), then folded into fp32 register
// accumulators with RN adds — reproducing the per-pass single-rounding
// structure validated in R7, at tensor-core speed.
#define GT   128
#define KC   32
#define TPAD 40                    // smem row stride in bf16 (conflict-free)
#define TILE_E (128 * TPAD)        // elements per slice tile
#define SMEM_E (6 * TILE_E)        // 3 A slices + 3 B slices
#define SMEM_B (SMEM_E * 2)

__device__ __forceinline__ void mma16816_c0(float* d, const uint32_t* a, const uint32_t* b) {
    asm volatile("mma.sync.aligned.m16n8k16.row.col.f32.bf16.bf16.f32 "
                 "{%0,%1,%2,%3}, {%4,%5,%6,%7}, {%8,%9}, {%10,%11,%12,%13};"
                 : "=f"(d[0]), "=f"(d[1]), "=f"(d[2]), "=f"(d[3])
                 : "r"(a[0]), "r"(a[1]), "r"(a[2]), "r"(a[3]),
                   "r"(b[0]), "r"(b[1]),
                   "f"(0.f), "f"(0.f), "f"(0.f), "f"(0.f));
}

__global__ __launch_bounds__(256, 1)
void gemm_mma9(const __nv_bfloat16* __restrict__ A0, const __nv_bfloat16* __restrict__ A1,
               const __nv_bfloat16* __restrict__ A2,
               const __nv_bfloat16* __restrict__ B0, const __nv_bfloat16* __restrict__ B1,
               const __nv_bfloat16* __restrict__ B2,
               const float* __restrict__ bias, float* __restrict__ C,
               int M, int N, int K)
{
    extern __shared__ __nv_bfloat16 sm[];
    __nv_bfloat16* As = sm;              // [3][128][TPAD]
    __nv_bfloat16* Bs = sm + 3 * TILE_E; // [3][128][TPAD]

    const int tid  = threadIdx.x;
    const int wid  = tid >> 5;
    const int lane = tid & 31;
    const int gid  = lane >> 2;          // 0..7
    const int tig  = lane & 3;           // 0..3
    const int bm   = blockIdx.y * GT;
    const int bn   = blockIdx.x * GT;
    const int wm   = (wid >> 2) * 64;    // warp M offset
    const int wn   = (wid & 3) * 32;     // warp N offset

    const __nv_bfloat16* Ag[3] = {A0, A1, A2};
    const __nv_bfloat16* Bg[3] = {B0, B1, B2};

    float acc[4][4][4];
#pragma unroll
    for (int i = 0; i < 4; i++)
#pragma unroll
        for (int j = 0; j < 4; j++)
#pragma unroll
            for (int q = 0; q < 4; q++) acc[i][j][q] = 0.f;

    const int nchunk = K / KC;
    for (int c = 0; c < nchunk; c++) {
        const int k0 = c * KC;
        // stage 6 tiles: 128 rows x 32 bf16 each (16B vector loads)
#pragma unroll
        for (int s = 0; s < 3; s++) {
#pragma unroll
            for (int q = 0; q < 2; q++) {
                int u   = tid + 256 * q;       // 512 16B units per tile
                int row = u >> 2;
                int cu  = u & 3;
                *(uint4*)&As[s * TILE_E + row * TPAD + cu * 8] =
                    *(const uint4*)(Ag[s] + (size_t)(bm + row) * K + k0 + cu * 8);
                *(uint4*)&Bs[s * TILE_E + row * TPAD + cu * 8] =
                    *(const uint4*)(Bg[s] + (size_t)(bn + row) * K + k0 + cu * 8);
            }
        }
        __syncthreads();

#pragma unroll
        for (int ks = 0; ks < 2; ks++) {
            const int kb = ks * 16;
            // load all slice fragments once, reuse across the 9 passes
            uint32_t afr[3][4][4], bfr[3][4][2];
#pragma unroll
            for (int s = 0; s < 3; s++) {
                const __nv_bfloat16* Ab = As + s * TILE_E;
                const __nv_bfloat16* Bb = Bs + s * TILE_E;
#pragma unroll
                for (int mf = 0; mf < 4; mf++) {
                    int r0 = wm + mf * 16 + gid;
                    afr[s][mf][0] = *(const uint32_t*)&Ab[r0 * TPAD + kb + 2 * tig];
                    afr[s][mf][1] = *(const uint32_t*)&Ab[(r0 + 8) * TPAD + kb + 2 * tig];
                    afr[s][mf][2] = *(const uint32_t*)&Ab[r0 * TPAD + kb + 2 * tig + 8];
                    afr[s][mf][3] = *(const uint32_t*)&Ab[(r0 + 8) * TPAD + kb + 2 * tig + 8];
                }
#pragma unroll
                for (int nf = 0; nf < 4; nf++) {
                    int nrow = wn + nf * 8 + gid;
                    bfr[s][nf][0] = *(const uint32_t*)&Bb[nrow * TPAD + kb + 2 * tig];
                    bfr[s][nf][1] = *(const uint32_t*)&Bb[nrow * TPAD + kb + 2 * tig + 8];
                }
            }
            // 9 slice-MMAs per k16, a-slice-major: hh,hm,hl,mh,mm,ml,lh,lm,ll.
            // Each with C=0, folded into fp32 regs with RN adds (R7 structure).
#pragma unroll
            for (int p = 0; p < 9; p++) {
                const int pa = p / 3, pb = p % 3;
#pragma unroll
                for (int mf = 0; mf < 4; mf++)
#pragma unroll
                    for (int nf = 0; nf < 4; nf++) {
                        float t[4];
                        mma16816_c0(t, afr[pa][mf], bfr[pb][nf]);
                        acc[mf][nf][0] = __fadd_rn(acc[mf][nf][0], t[0]);
                        acc[mf][nf][1] = __fadd_rn(acc[mf][nf][1], t[1]);
                        acc[mf][nf][2] = __fadd_rn(acc[mf][nf][2], t[2]);
                        acc[mf][nf][3] = __fadd_rn(acc[mf][nf][3], t[3]);
                    }
            }
        }
        __syncthreads();
    }

    // epilogue: c0,c1 -> (row, col..col+1), c2,c3 -> (row+8, ...)
    const bool hb = (bias != nullptr);
#pragma unroll
    for (int mf = 0; mf < 4; mf++) {
#pragma unroll
        for (int nf = 0; nf < 4; nf++) {
            int row = bm + wm + mf * 16 + gid;
            int col = bn + wn + nf * 8 + 2 * tig;
            float v0 = acc[mf][nf][0], v1 = acc[mf][nf][1];
            float v2 = acc[mf][nf][2], v3 = acc[mf][nf][3];
            if (hb) {
                float bb0 = bias[col], bb1 = bias[col + 1];
                v0 = __fadd_rn(v0, bb0); v1 = __fadd_rn(v1, bb1);
                v2 = __fadd_rn(v2, bb0); v3 = __fadd_rn(v3, bb1);
            }
            *(float2*)&C[(size_t)row * N + col]       = make_float2(v0, v1);
            *(float2*)&C[(size_t)(row + 8) * N + col] = make_float2(v2, v3);
        }
    }
}

// ---------------- gating + exact k-winners (+ fused h split) ----------------
__global__ __launch_bounds__(256)
void gate_topk(const float* __restrict__ y, const float* __restrict__ dend,
               __nv_bfloat16* __restrict__ hh, __nv_bfloat16* __restrict__ hm,
               __nv_bfloat16* __restrict__ hl)
{
    __shared__ float     vals[HID];
    __shared__ unsigned  keys[HID];
    __shared__ int       hist[256];
    __shared__ unsigned  s_prefix;
    __shared__ int       s_remaining;

    const int b   = blockIdx.x;
    const int tid = threadIdx.x;
    const float* drow = dend + (size_t)b * HID * NSEG;
    const float* yrow = y    + (size_t)b * HID;

    for (int h = tid; h < HID; h += 256) {
        float best = 0.f, bestabs = -1.f;
#pragma unroll
        for (int s = 0; s < NSEG; s++) {
            float v = drow[h * NSEG + s];
            float a = fabsf(v);
            if (a > bestabs) { bestabs = a; best = v; }  // first-occurrence argmax
        }
        float g = yrow[h] * (1.f / (1.f + expf(-best)));
        vals[h] = g;
        unsigned u = __float_as_uint(g);
        keys[h] = (u & 0x80000000u) ? ~u : (u | 0x80000000u);
    }
    if (tid == 0) { s_prefix = 0u; s_remaining = KWIN; }
    __syncthreads();

    for (int d = 3; d >= 0; d--) {
        hist[tid] = 0;
        __syncthreads();
        const unsigned pmask = (d == 3) ? 0u : (0xFFFFFFFFu << ((d + 1) * 8));
        const unsigned pref  = s_prefix;
        const int shift = d * 8;
        for (int h = tid; h < HID; h += 256) {
            unsigned kk = keys[h];
            if ((kk & pmask) == pref)
                atomicAdd(&hist[(kk >> shift) & 0xFF], 1);
        }
        __syncthreads();
        if (tid == 0) {
            int rem = s_remaining, cum = 0, bkt = 255;
            for (; bkt > 0; bkt--) {
                int c = hist[bkt];
                if (cum + c >= rem) break;
                cum += c;
            }
            s_remaining = rem - cum;
            s_prefix    = pref | ((unsigned)bkt << shift);
        }
        __syncthreads();
    }

    const unsigned kth = s_prefix;
    for (int h = tid; h < HID; h += 256) {
        float v = (keys[h] >= kth) ? vals[h] : 0.f;
        size_t o = (size_t)b * HID + h;
        __nv_bfloat16 hb = __float2bfloat16(v);
        float hf = __bfloat162float(hb);
        float r1 = v - hf;
        __nv_bfloat16 mb = __float2bfloat16(r1);
        float r2 = r1 - __bfloat162float(mb);
        hh[o] = hb; hm[o] = mb; hl[o] = __float2bfloat16(r2);
    }
}

// ---------------- launch -----------------------------------------------------
extern "C" void kernel_launch(void* const* d_in, const int* in_sizes, int n_in,
                              void* d_out, int out_size)
{
    (void)in_sizes; (void)n_in; (void)out_size;
    const float* x     = (const float*)d_in[0];
    const float* ctx   = (const float*)d_in[1];
    const float* w1    = (const float*)d_in[2];
    const float* b1    = (const float*)d_in[3];
    const float* seg1  = (const float*)d_in[4];
    const float* w2    = (const float*)d_in[5];
    const float* b2    = (const float*)d_in[6];
    const float* seg2  = (const float*)d_in[7];
    const float* w_out = (const float*)d_in[8];
    const float* b_out = (const float*)d_in[9];
    float* out = (float*)d_out;

    float *dendp, *yp;
    cudaGetSymbolAddress((void**)&dendp, g_dend);
    cudaGetSymbolAddress((void**)&yp,    g_y);
    __nv_bfloat16 *xs, *cs, *w1s, *s1s, *w2s, *s2s, *wos, *hs;
    cudaGetSymbolAddress((void**)&xs,  g_xs);
    cudaGetSymbolAddress((void**)&cs,  g_cs);
    cudaGetSymbolAddress((void**)&w1s, g_w1s);
    cudaGetSymbolAddress((void**)&s1s, g_s1s);
    cudaGetSymbolAddress((void**)&w2s, g_w2s);
    cudaGetSymbolAddress((void**)&s2s, g_s2s);
    cudaGetSymbolAddress((void**)&wos, g_wos);
    cudaGetSymbolAddress((void**)&hs,  g_hs);

    const size_t nx = (size_t)B_SZ * D_IN,  nc = (size_t)B_SZ * D_CTX;
    const size_t n1 = (size_t)HID * D_IN,   ns = (size_t)HID * NSEG * D_CTX;
    const size_t n2 = (size_t)HID * HID,    no = (size_t)D_OUT * HID;
    const size_t nh = (size_t)B_SZ * HID;

    cudaFuncSetAttribute(gemm_mma9, cudaFuncAttributeMaxDynamicSharedMemorySize, SMEM_B);

    split_kernel<<<2048, 256>>>(x,     xs,  xs + nx,  xs + 2*nx,  nx);
    split_kernel<<<2048, 256>>>(ctx,   cs,  cs + nc,  cs + 2*nc,  nc);
    split_kernel<<<2048, 256>>>(w1,    w1s, w1s + n1, w1s + 2*n1, n1);
    split_kernel<<<4096, 256>>>(seg1,  s1s, s1s + ns, s1s + 2*ns, ns);
    split_kernel<<<2048, 256>>>(w2,    w2s, w2s + n2, w2s + 2*n2, n2);
    split_kernel<<<4096, 256>>>(seg2,  s2s, s2s + ns, s2s + 2*ns, ns);
    split_kernel<<<2048, 256>>>(w_out, wos, wos + no, wos + 2*no, no);

    // layer 1
    gemm_mma9<<<dim3(HID / GT, B_SZ / GT), 256, SMEM_B>>>(
        xs, xs + nx, xs + 2*nx, w1s, w1s + n1, w1s + 2*n1, b1, yp, B_SZ, HID, D_IN);
    gemm_mma9<<<dim3(HID * NSEG / GT, B_SZ / GT), 256, SMEM_B>>>(
        cs, cs + nc, cs + 2*nc, s1s, s1s + ns, s1s + 2*ns, nullptr, dendp, B_SZ, HID * NSEG, D_CTX);
    gate_topk<<<B_SZ, 256>>>(yp, dendp, hs, hs + nh, hs + 2*nh);

    // layer 2
    gemm_mma9<<<dim3(HID / GT, B_SZ / GT), 256, SMEM_B>>>(
        hs, hs + nh, hs + 2*nh, w2s, w2s + n2, w2s + 2*n2, b2, yp, B_SZ, HID, HID);
    gemm_mma9<<<dim3(HID * NSEG / GT, B_SZ / GT), 256, SMEM_B>>>(
        cs, cs + nc, cs + 2*nc, s2s, s2s + ns, s2s + 2*ns, nullptr, dendp, B_SZ, HID * NSEG, D_CTX);
    gate_topk<<<B_SZ, 256>>>(yp, dendp, hs, hs + nh, hs + 2*nh);

    // output projection
    gemm_mma9<<<dim3(D_OUT / GT, B_SZ / GT), 256, SMEM_B>>>(
        hs, hs + nh, hs + 2*nh, wos, wos + no, wos + 2*no, b_out, out, B_SZ, D_OUT, HID);
}

// round 11
// speedup vs baseline: 505.1975x; 1.4498x over previous
#include <cuda_runtime.h>
#include <cuda_bf16.h>
#include <math.h>
#include <stdint.h>

#define B_SZ  4096
#define D_IN  1024
#define HID   2048
#define NSEG  10
#define D_CTX 1024
#define D_OUT 1024
#define KWIN  102

// ---------------- scratch (device globals, allocation-free) ----------------
__device__ float g_dend[(size_t)B_SZ * HID * NSEG]; // 4096 x 20480  (~335 MB)
__device__ float g_y[(size_t)B_SZ * HID];           // pre-gate linear output

// bf16 hi/mid/lo splits of every GEMM operand (exact 3-way decomposition)
__device__ __nv_bfloat16 g_xs [3][(size_t)B_SZ * D_IN];
__device__ __nv_bfloat16 g_cs [3][(size_t)B_SZ * D_CTX];
__device__ __nv_bfloat16 g_w1s[3][(size_t)HID * D_IN];
__device__ __nv_bfloat16 g_s1s[3][(size_t)HID * NSEG * D_CTX];
__device__ __nv_bfloat16 g_w2s[3][(size_t)HID * HID];
__device__ __nv_bfloat16 g_s2s[3][(size_t)HID * NSEG * D_CTX];
__device__ __nv_bfloat16 g_wos[3][(size_t)D_OUT * HID];
__device__ __nv_bfloat16 g_hs [3][(size_t)B_SZ * HID];

// ---------------- bf16 3-way split ------------------------------------------
__global__ void split_kernel(const float* __restrict__ src,
                             __nv_bfloat16* __restrict__ hh,
                             __nv_bfloat16* __restrict__ mm,
                             __nv_bfloat16* __restrict__ ll, size_t n)
{
    for (size_t i = (size_t)blockIdx.x * blockDim.x + threadIdx.x; i < n;
         i += (size_t)gridDim.x * blockDim.x) {
        float a = src[i];
        __nv_bfloat16 hb = __float2bfloat16(a);
        float hf = __bfloat162float(hb);
        float r1 = a - hf;                         // exact
        __nv_bfloat16 mb = __float2bfloat16(r1);
        float mf = __bfloat162float(mb);
        float r2 = r1 - mf;                        // exact
        hh[i] = hb; mm[i] = mb; ll[i] = __float2bfloat16(r2);
    }
}

// ---------------- cp.async helpers ------------------------------------------
__device__ __forceinline__ void cp16(void* sdst, const void* gsrc) {
    uint32_t s = (uint32_t)__cvta_generic_to_shared(sdst);
    asm volatile("cp.async.cg.shared.global [%0], [%1], 16;" :: "r"(s), "l"(gsrc));
}
#define CP_COMMIT() asm volatile("cp.async.commit_group;" ::: "memory")
#define CP_WAIT(n)  asm volatile("cp.async.wait_group %0;" :: "n"(n) : "memory")

// ---------------- bf16 HMMA x6 GEMM: C = A @ B^T (+bias) --------------------
// A,B pre-split hi/mid/lo bf16, [rows, K] row-major. CTA tile 128x128,
// 8 warps of 64x32, cp.async double-buffered K-chunks of 32.
// Per k16: 6 slice-MMAs (hh,hm,hl,mh,mm,lh — the significance-relevant subset
// of the validated 9-pass order; dropped ml/lm/ll perturb dots by ~3e-8 rel,
// ~+7e-6 on final rel_err per the measured x233 amplification).
// Each MMA issued with C=0, folded into fp32 regs with RN adds (R7 structure).
#define GT   128
#define KC   32
#define TPAD 40                    // smem row stride in bf16 (conflict-free)
#define TILE_E (128 * TPAD)        // elements per slice tile
#define BUF_E  (6 * TILE_E)        // 3 A slices + 3 B slices
#define SMEM_B (2 * BUF_E * 2)     // 2 buffers, bytes

__device__ __forceinline__ void mma16816_c0(float* d, const uint32_t* a, const uint32_t* b) {
    asm volatile("mma.sync.aligned.m16n8k16.row.col.f32.bf16.bf16.f32 "
                 "{%0,%1,%2,%3}, {%4,%5,%6,%7}, {%8,%9}, {%10,%11,%12,%13};"
                 : "=f"(d[0]), "=f"(d[1]), "=f"(d[2]), "=f"(d[3])
                 : "r"(a[0]), "r"(a[1]), "r"(a[2]), "r"(a[3]),
                   "r"(b[0]), "r"(b[1]),
                   "f"(0.f), "f"(0.f), "f"(0.f), "f"(0.f));
}

__device__ __forceinline__ void preload_chunk(
    __nv_bfloat16* buf, const __nv_bfloat16* const* Ag, const __nv_bfloat16* const* Bg,
    int bm, int bn, int K, int k0, int tid)
{
#pragma unroll
    for (int s = 0; s < 3; s++) {
#pragma unroll
        for (int q = 0; q < 2; q++) {
            int u   = tid + 256 * q;       // 512 16B units per tile
            int row = u >> 2;
            int cu  = u & 3;
            cp16(&buf[s * TILE_E + row * TPAD + cu * 8],
                 Ag[s] + (size_t)(bm + row) * K + k0 + cu * 8);
            cp16(&buf[(3 + s) * TILE_E + row * TPAD + cu * 8],
                 Bg[s] + (size_t)(bn + row) * K + k0 + cu * 8);
        }
    }
}

__global__ __launch_bounds__(256, 1)
void gemm_mma6(const __nv_bfloat16* __restrict__ A0, const __nv_bfloat16* __restrict__ A1,
               const __nv_bfloat16* __restrict__ A2,
               const __nv_bfloat16* __restrict__ B0, const __nv_bfloat16* __restrict__ B1,
               const __nv_bfloat16* __restrict__ B2,
               const float* __restrict__ bias, float* __restrict__ C,
               int M, int N, int K)
{
    extern __shared__ __nv_bfloat16 sm[];

    const int tid  = threadIdx.x;
    const int wid  = tid >> 5;
    const int lane = tid & 31;
    const int gid  = lane >> 2;          // 0..7
    const int tig  = lane & 3;           // 0..3
    const int bm   = blockIdx.y * GT;
    const int bn   = blockIdx.x * GT;
    const int wm   = (wid >> 2) * 64;    // warp M offset
    const int wn   = (wid & 3) * 32;     // warp N offset

    const __nv_bfloat16* Ag[3] = {A0, A1, A2};
    const __nv_bfloat16* Bg[3] = {B0, B1, B2};

    float acc[4][4][4];
#pragma unroll
    for (int i = 0; i < 4; i++)
#pragma unroll
        for (int j = 0; j < 4; j++)
#pragma unroll
            for (int q = 0; q < 4; q++) acc[i][j][q] = 0.f;

    const int nchunk = K / KC;

    preload_chunk(sm, Ag, Bg, bm, bn, K, 0, tid);
    CP_COMMIT();
    if (nchunk > 1) {
        preload_chunk(sm + BUF_E, Ag, Bg, bm, bn, K, KC, tid);
        CP_COMMIT();
    }

    for (int c = 0; c < nchunk; c++) {
        if (c + 1 < nchunk) { CP_WAIT(1); } else { CP_WAIT(0); }
        __syncthreads();

        __nv_bfloat16* As = sm + (c & 1) * BUF_E;
        __nv_bfloat16* Bs = As + 3 * TILE_E;

#pragma unroll
        for (int ks = 0; ks < 2; ks++) {
            const int kb = ks * 16;
            // load all slice fragments once, reuse across the 6 passes
            uint32_t afr[3][4][4], bfr[3][4][2];
#pragma unroll
            for (int s = 0; s < 3; s++) {
                const __nv_bfloat16* Ab = As + s * TILE_E;
                const __nv_bfloat16* Bb = Bs + s * TILE_E;
#pragma unroll
                for (int mf = 0; mf < 4; mf++) {
                    int r0 = wm + mf * 16 + gid;
                    afr[s][mf][0] = *(const uint32_t*)&Ab[r0 * TPAD + kb + 2 * tig];
                    afr[s][mf][1] = *(const uint32_t*)&Ab[(r0 + 8) * TPAD + kb + 2 * tig];
                    afr[s][mf][2] = *(const uint32_t*)&Ab[r0 * TPAD + kb + 2 * tig + 8];
                    afr[s][mf][3] = *(const uint32_t*)&Ab[(r0 + 8) * TPAD + kb + 2 * tig + 8];
                }
#pragma unroll
                for (int nf = 0; nf < 4; nf++) {
                    int nrow = wn + nf * 8 + gid;
                    bfr[s][nf][0] = *(const uint32_t*)&Bb[nrow * TPAD + kb + 2 * tig];
                    bfr[s][nf][1] = *(const uint32_t*)&Bb[nrow * TPAD + kb + 2 * tig + 8];
                }
            }
            // 6 slice-MMAs per k16: hh,hm,hl,mh,mm,lh (R7 relative order)
            const int PA[6] = {0, 0, 0, 1, 1, 2};
            const int PB[6] = {0, 1, 2, 0, 1, 0};
#pragma unroll
            for (int p = 0; p < 6; p++) {
                const int pa = PA[p], pb = PB[p];
#pragma unroll
                for (int mf = 0; mf < 4; mf++)
#pragma unroll
                    for (int nf = 0; nf < 4; nf++) {
                        float t[4];
                        mma16816_c0(t, afr[pa][mf], bfr[pb][nf]);
                        acc[mf][nf][0] = __fadd_rn(acc[mf][nf][0], t[0]);
                        acc[mf][nf][1] = __fadd_rn(acc[mf][nf][1], t[1]);
                        acc[mf][nf][2] = __fadd_rn(acc[mf][nf][2], t[2]);
                        acc[mf][nf][3] = __fadd_rn(acc[mf][nf][3], t[3]);
                    }
            }
        }
        __syncthreads();
        if (c + 2 < nchunk) {
            preload_chunk(sm + (c & 1) * BUF_E, Ag, Bg, bm, bn, K, (c + 2) * KC, tid);
            CP_COMMIT();
        }
    }

    // epilogue: c0,c1 -> (row, col..col+1), c2,c3 -> (row+8, ...)
    const bool hb = (bias != nullptr);
#pragma unroll
    for (int mf = 0; mf < 4; mf++) {
#pragma unroll
        for (int nf = 0; nf < 4; nf++) {
            int row = bm + wm + mf * 16 + gid;
            int col = bn + wn + nf * 8 + 2 * tig;
            float v0 = acc[mf][nf][0], v1 = acc[mf][nf][1];
            float v2 = acc[mf][nf][2], v3 = acc[mf][nf][3];
            if (hb) {
                float bb0 = bias[col], bb1 = bias[col + 1];
                v0 = __fadd_rn(v0, bb0); v1 = __fadd_rn(v1, bb1);
                v2 = __fadd_rn(v2, bb0); v3 = __fadd_rn(v3, bb1);
            }
            *(float2*)&C[(size_t)row * N + col]       = make_float2(v0, v1);
            *(float2*)&C[(size_t)(row + 8) * N + col] = make_float2(v2, v3);
        }
    }
}

// ---------------- gating + exact k-winners (+ fused h split) ----------------
__global__ __launch_bounds__(256)
void gate_topk(const float* __restrict__ y, const float* __restrict__ dend,
               __nv_bfloat16* __restrict__ hh, __nv_bfloat16* __restrict__ hm,
               __nv_bfloat16* __restrict__ hl)
{
    __shared__ float     vals[HID];
    __shared__ unsigned  keys[HID];
    __shared__ int       hist[256];
    __shared__ unsigned  s_prefix;
    __shared__ int       s_remaining;

    const int b   = blockIdx.x;
    const int tid = threadIdx.x;
    const float* drow = dend + (size_t)b * HID * NSEG;
    const float* yrow = y    + (size_t)b * HID;

    for (int h = tid; h < HID; h += 256) {
        float best = 0.f, bestabs = -1.f;
#pragma unroll
        for (int s = 0; s < NSEG; s++) {
            float v = drow[h * NSEG + s];
            float a = fabsf(v);
            if (a > bestabs) { bestabs = a; best = v; }  // first-occurrence argmax
        }
        float g = yrow[h] * (1.f / (1.f + expf(-best)));
        vals[h] = g;
        unsigned u = __float_as_uint(g);
        keys[h] = (u & 0x80000000u) ? ~u : (u | 0x80000000u);
    }
    if (tid == 0) { s_prefix = 0u; s_remaining = KWIN; }
    __syncthreads();

    for (int d = 3; d >= 0; d--) {
        hist[tid] = 0;
        __syncthreads();
        const unsigned pmask = (d == 3) ? 0u : (0xFFFFFFFFu << ((d + 1) * 8));
        const unsigned pref  = s_prefix;
        const int shift = d * 8;
        for (int h = tid; h < HID; h += 256) {
            unsigned kk = keys[h];
            if ((kk & pmask) == pref)
                atomicAdd(&hist[(kk >> shift) & 0xFF], 1);
        }
        __syncthreads();
        if (tid == 0) {
            int rem = s_remaining, cum = 0, bkt = 255;
            for (; bkt > 0; bkt--) {
                int c = hist[bkt];
                if (cum + c >= rem) break;
                cum += c;
            }
            s_remaining = rem - cum;
            s_prefix    = pref | ((unsigned)bkt << shift);
        }
        __syncthreads();
    }

    const unsigned kth = s_prefix;
    for (int h = tid; h < HID; h += 256) {
        float v = (keys[h] >= kth) ? vals[h] : 0.f;
        size_t o = (size_t)b * HID + h;
        __nv_bfloat16 hb = __float2bfloat16(v);
        float hf = __bfloat162float(hb);
        float r1 = v - hf;
        __nv_bfloat16 mb = __float2bfloat16(r1);
        float r2 = r1 - __bfloat162float(mb);
        hh[o] = hb; hm[o] = mb; hl[o] = __float2bfloat16(r2);
    }
}

// ---------------- launch -----------------------------------------------------
extern "C" void kernel_launch(void* const* d_in, const int* in_sizes, int n_in,
                              void* d_out, int out_size)
{
    (void)in_sizes; (void)n_in; (void)out_size;
    const float* x     = (const float*)d_in[0];
    const float* ctx   = (const float*)d_in[1];
    const float* w1    = (const float*)d_in[2];
    const float* b1    = (const float*)d_in[3];
    const float* seg1  = (const float*)d_in[4];
    const float* w2    = (const float*)d_in[5];
    const float* b2    = (const float*)d_in[6];
    const float* seg2  = (const float*)d_in[7];
    const float* w_out = (const float*)d_in[8];
    const float* b_out = (const float*)d_in[9];
    float* out = (float*)d_out;

    float *dendp, *yp;
    cudaGetSymbolAddress((void**)&dendp, g_dend);
    cudaGetSymbolAddress((void**)&yp,    g_y);
    __nv_bfloat16 *xs, *cs, *w1s, *s1s, *w2s, *s2s, *wos, *hs;
    cudaGetSymbolAddress((void**)&xs,  g_xs);
    cudaGetSymbolAddress((void**)&cs,  g_cs);
    cudaGetSymbolAddress((void**)&w1s, g_w1s);
    cudaGetSymbolAddress((void**)&s1s, g_s1s);
    cudaGetSymbolAddress((void**)&w2s, g_w2s);
    cudaGetSymbolAddress((void**)&s2s, g_s2s);
    cudaGetSymbolAddress((void**)&wos, g_wos);
    cudaGetSymbolAddress((void**)&hs,  g_hs);

    const size_t nx = (size_t)B_SZ * D_IN,  nc = (size_t)B_SZ * D_CTX;
    const size_t n1 = (size_t)HID * D_IN,   ns = (size_t)HID * NSEG * D_CTX;
    const size_t n2 = (size_t)HID * HID,    no = (size_t)D_OUT * HID;
    const size_t nh = (size_t)B_SZ * HID;

    cudaFuncSetAttribute(gemm_mma6, cudaFuncAttributeMaxDynamicSharedMemorySize, SMEM_B);

    split_kernel<<<2048, 256>>>(x,     xs,  xs + nx,  xs + 2*nx,  nx);
    split_kernel<<<2048, 256>>>(ctx,   cs,  cs + nc,  cs + 2*nc,  nc);
    split_kernel<<<2048, 256>>>(w1,    w1s, w1s + n1, w1s + 2*n1, n1);
    split_kernel<<<4096, 256>>>(seg1,  s1s, s1s + ns, s1s + 2*ns, ns);
    split_kernel<<<2048, 256>>>(w2,    w2s, w2s + n2, w2s + 2*n2, n2);
    split_kernel<<<4096, 256>>>(seg2,  s2s, s2s + ns, s2s + 2*ns, ns);
    split_kernel<<<2048, 256>>>(w_out, wos, wos + no, wos + 2*no, no);

    // layer 1
    gemm_mma6<<<dim3(HID / GT, B_SZ / GT), 256, SMEM_B>>>(
        xs, xs + nx, xs + 2*nx, w1s, w1s + n1, w1s + 2*n1, b1, yp, B_SZ, HID, D_IN);
    gemm_mma6<<<dim3(HID * NSEG / GT, B_SZ / GT), 256, SMEM_B>>>(
        cs, cs + nc, cs + 2*nc, s1s, s1s + ns, s1s + 2*ns, nullptr, dendp, B_SZ, HID * NSEG, D_CTX);
    gate_topk<<<B_SZ, 256>>>(yp, dendp, hs, hs + nh, hs + 2*nh);

    // layer 2
    gemm_mma6<<<dim3(HID / GT, B_SZ / GT), 256, SMEM_B>>>(
        hs, hs + nh, hs + 2*nh, w2s, w2s + n2, w2s + 2*n2, b2, yp, B_SZ, HID, HID);
    gemm_mma6<<<dim3(HID * NSEG / GT, B_SZ / GT), 256, SMEM_B>>>(
        cs, cs + nc, cs + 2*nc, s2s, s2s + ns, s2s + 2*ns, nullptr, dendp, B_SZ, HID * NSEG, D_CTX);
    gate_topk<<<B_SZ, 256>>>(yp, dendp, hs, hs + nh, hs + 2*nh);

    // output projection
    gemm_mma6<<<dim3(D_OUT / GT, B_SZ / GT), 256, SMEM_B>>>(
        hs, hs + nh, hs + 2*nh, wos, wos + no, wos + 2*no, b_out, out, B_SZ, D_OUT, HID);
}

// round 13
// speedup vs baseline: 546.9133x; 1.0826x over previous
#include <cuda_runtime.h>
#include <cuda_bf16.h>
#include <math.h>
#include <stdint.h>

#define B_SZ  4096
#define D_IN  1024
#define HID   2048
#define NSEG  10
#define D_CTX 1024
#define D_OUT 1024
#define KWIN  102

// ---------------- scratch (device globals, allocation-free) ----------------
__device__ float g_dend[(size_t)B_SZ * HID * NSEG]; // 4096 x 20480  (~335 MB)
__device__ float g_y[(size_t)B_SZ * HID];           // pre-gate linear output

// bf16 hi/mid/lo splits of every GEMM operand (exact 3-way decomposition)
__device__ __nv_bfloat16 g_xs [3][(size_t)B_SZ * D_IN];
__device__ __nv_bfloat16 g_cs [3][(size_t)B_SZ * D_CTX];
__device__ __nv_bfloat16 g_w1s[3][(size_t)HID * D_IN];
__device__ __nv_bfloat16 g_s1s[3][(size_t)HID * NSEG * D_CTX];
__device__ __nv_bfloat16 g_w2s[3][(size_t)HID * HID];
__device__ __nv_bfloat16 g_s2s[3][(size_t)HID * NSEG * D_CTX];
__device__ __nv_bfloat16 g_wos[3][(size_t)D_OUT * HID];
__device__ __nv_bfloat16 g_hs [3][(size_t)B_SZ * HID];

// ---------------- bf16 3-way split (float4-vectorized) ----------------------
__global__ void split_kernel(const float* __restrict__ src,
                             __nv_bfloat16* __restrict__ hh,
                             __nv_bfloat16* __restrict__ mm,
                             __nv_bfloat16* __restrict__ ll, size_t n)
{
    const size_t n4 = n >> 2;
    for (size_t i = (size_t)blockIdx.x * blockDim.x + threadIdx.x; i < n4;
         i += (size_t)gridDim.x * blockDim.x) {
        float4 a = ((const float4*)src)[i];
        float av[4] = {a.x, a.y, a.z, a.w};
        __nv_bfloat16 hv[4], mv[4], lv[4];
#pragma unroll
        for (int j = 0; j < 4; j++) {
            float v = av[j];
            __nv_bfloat16 hb = __float2bfloat16(v);
            float hf = __bfloat162float(hb);
            float r1 = v - hf;                       // exact
            __nv_bfloat16 mb = __float2bfloat16(r1);
            float r2 = r1 - __bfloat162float(mb);    // exact
            hv[j] = hb; mv[j] = mb; lv[j] = __float2bfloat16(r2);
        }
        size_t o = i * 4;
        *(__nv_bfloat162*)&hh[o]     = __nv_bfloat162(hv[0], hv[1]);
        *(__nv_bfloat162*)&hh[o + 2] = __nv_bfloat162(hv[2], hv[3]);
        *(__nv_bfloat162*)&mm[o]     = __nv_bfloat162(mv[0], mv[1]);
        *(__nv_bfloat162*)&mm[o + 2] = __nv_bfloat162(mv[2], mv[3]);
        *(__nv_bfloat162*)&ll[o]     = __nv_bfloat162(lv[0], lv[1]);
        *(__nv_bfloat162*)&ll[o + 2] = __nv_bfloat162(lv[2], lv[3]);
    }
}

// ---------------- cp.async helpers ------------------------------------------
__device__ __forceinline__ void cp16(void* sdst, const void* gsrc) {
    uint32_t s = (uint32_t)__cvta_generic_to_shared(sdst);
    asm volatile("cp.async.cg.shared.global [%0], [%1], 16;" :: "r"(s), "l"(gsrc));
}
#define CP_COMMIT() asm volatile("cp.async.commit_group;" ::: "memory")
#define CP_WAIT(n)  asm volatile("cp.async.wait_group %0;" :: "n"(n) : "memory")

// ---------------- bf16 HMMA x6 GEMM: C = A @ B^T (+bias) --------------------
// FROZEN NUMERICS (validated R7/R10/R11; any rounding-structure change flips
// the knife-edge top-k decision — see R12): per k16, 6 slice-MMAs in order
// hh,hm,hl,mh,mm,lh, each issued with C=0 and folded into fp32 registers with
// 4 RN adds. Triple-buffered cp.async K-chunks of 32 (pipelining only; the
// per-element arithmetic sequence is bit-identical to R11).
#define GT   128
#define KC   32
#define NSTG 3
#define TPAD 40                    // smem row stride in bf16 (conflict-free)
#define TILE_E (128 * TPAD)        // elements per slice tile
#define BUF_E  (6 * TILE_E)        // 3 A slices + 3 B slices
#define SMEM_B (NSTG * BUF_E * 2)  // bytes (184320)

__device__ __forceinline__ void mma16816_c0(float* d, const uint32_t* a, const uint32_t* b) {
    asm volatile("mma.sync.aligned.m16n8k16.row.col.f32.bf16.bf16.f32 "
                 "{%0,%1,%2,%3}, {%4,%5,%6,%7}, {%8,%9}, {%10,%11,%12,%13};"
                 : "=f"(d[0]), "=f"(d[1]), "=f"(d[2]), "=f"(d[3])
                 : "r"(a[0]), "r"(a[1]), "r"(a[2]), "r"(a[3]),
                   "r"(b[0]), "r"(b[1]),
                   "f"(0.f), "f"(0.f), "f"(0.f), "f"(0.f));
}

__device__ __forceinline__ void preload_chunk(
    __nv_bfloat16* buf, const __nv_bfloat16* const* Ag, const __nv_bfloat16* const* Bg,
    int bm, int bn, int K, int k0, int tid)
{
#pragma unroll
    for (int s = 0; s < 3; s++) {
#pragma unroll
        for (int q = 0; q < 2; q++) {
            int u   = tid + 256 * q;       // 512 16B units per tile
            int row = u >> 2;
            int cu  = u & 3;
            cp16(&buf[s * TILE_E + row * TPAD + cu * 8],
                 Ag[s] + (size_t)(bm + row) * K + k0 + cu * 8);
            cp16(&buf[(3 + s) * TILE_E + row * TPAD + cu * 8],
                 Bg[s] + (size_t)(bn + row) * K + k0 + cu * 8);
        }
    }
}

__global__ __launch_bounds__(256, 1)
void gemm_mma6(const __nv_bfloat16* __restrict__ A0, const __nv_bfloat16* __restrict__ A1,
               const __nv_bfloat16* __restrict__ A2,
               const __nv_bfloat16* __restrict__ B0, const __nv_bfloat16* __restrict__ B1,
               const __nv_bfloat16* __restrict__ B2,
               const float* __restrict__ bias, float* __restrict__ C,
               int M, int N, int K)
{
    extern __shared__ __nv_bfloat16 sm[];

    const int tid  = threadIdx.x;
    const int wid  = tid >> 5;
    const int lane = tid & 31;
    const int gid  = lane >> 2;          // 0..7
    const int tig  = lane & 3;           // 0..3
    const int bm   = blockIdx.y * GT;
    const int bn   = blockIdx.x * GT;
    const int wm   = (wid >> 2) * 64;    // warp M offset
    const int wn   = (wid & 3) * 32;     // warp N offset

    const __nv_bfloat16* Ag[3] = {A0, A1, A2};
    const __nv_bfloat16* Bg[3] = {B0, B1, B2};

    float acc[4][4][4];
#pragma unroll
    for (int i = 0; i < 4; i++)
#pragma unroll
        for (int j = 0; j < 4; j++)
#pragma unroll
            for (int q = 0; q < 4; q++) acc[i][j][q] = 0.f;

    const int nchunk = K / KC;   // >= 32 for all shapes here

    // prologue: stage chunks 0,1,2 (group j == chunk j)
    preload_chunk(sm,             Ag, Bg, bm, bn, K, 0,      tid); CP_COMMIT();
    preload_chunk(sm + BUF_E,     Ag, Bg, bm, bn, K, KC,     tid); CP_COMMIT();
    preload_chunk(sm + 2 * BUF_E, Ag, Bg, bm, bn, K, 2 * KC, tid); CP_COMMIT();

    int sbuf = 0;
    for (int c = 0; c < nchunk; c++) {
        CP_WAIT(2);              // all but newest 2 groups done => chunk c ready
        __syncthreads();

        __nv_bfloat16* As = sm + sbuf * BUF_E;
        __nv_bfloat16* Bs = As + 3 * TILE_E;

#pragma unroll
        for (int ks = 0; ks < 2; ks++) {
            const int kb = ks * 16;
            // load all slice fragments once, reuse across the passes
            uint32_t afr[3][4][4], bfr[3][4][2];
#pragma unroll
            for (int s = 0; s < 3; s++) {
                const __nv_bfloat16* Ab = As + s * TILE_E;
                const __nv_bfloat16* Bb = Bs + s * TILE_E;
#pragma unroll
                for (int mf = 0; mf < 4; mf++) {
                    int r0 = wm + mf * 16 + gid;
                    afr[s][mf][0] = *(const uint32_t*)&Ab[r0 * TPAD + kb + 2 * tig];
                    afr[s][mf][1] = *(const uint32_t*)&Ab[(r0 + 8) * TPAD + kb + 2 * tig];
                    afr[s][mf][2] = *(const uint32_t*)&Ab[r0 * TPAD + kb + 2 * tig + 8];
                    afr[s][mf][3] = *(const uint32_t*)&Ab[(r0 + 8) * TPAD + kb + 2 * tig + 8];
                }
#pragma unroll
                for (int nf = 0; nf < 4; nf++) {
                    int nrow = wn + nf * 8 + gid;
                    bfr[s][nf][0] = *(const uint32_t*)&Bb[nrow * TPAD + kb + 2 * tig];
                    bfr[s][nf][1] = *(const uint32_t*)&Bb[nrow * TPAD + kb + 2 * tig + 8];
                }
            }
            // 6 slice-MMAs per k16: hh,hm,hl,mh,mm,lh — each C=0 + RN folds
            const int PA[6] = {0, 0, 0, 1, 1, 2};
            const int PB[6] = {0, 1, 2, 0, 1, 0};
#pragma unroll
            for (int p = 0; p < 6; p++) {
                const int pa = PA[p], pb = PB[p];
#pragma unroll
                for (int mf = 0; mf < 4; mf++)
#pragma unroll
                    for (int nf = 0; nf < 4; nf++) {
                        float t[4];
                        mma16816_c0(t, afr[pa][mf], bfr[pb][nf]);
                        acc[mf][nf][0] = __fadd_rn(acc[mf][nf][0], t[0]);
                        acc[mf][nf][1] = __fadd_rn(acc[mf][nf][1], t[1]);
                        acc[mf][nf][2] = __fadd_rn(acc[mf][nf][2], t[2]);
                        acc[mf][nf][3] = __fadd_rn(acc[mf][nf][3], t[3]);
                    }
            }
        }
        __syncthreads();
        // always commit one group per iteration (empty at tail) so that
        // CP_WAIT(2) at iter c always has exactly groups c+1, c+2 newer.
        if (c + 3 < nchunk)
            preload_chunk(sm + sbuf * BUF_E, Ag, Bg, bm, bn, K, (c + 3) * KC, tid);
        CP_COMMIT();
        sbuf = (sbuf == NSTG - 1) ? 0 : sbuf + 1;
    }

    // epilogue: c0,c1 -> (row, col..col+1), c2,c3 -> (row+8, ...)
    const bool hb = (bias != nullptr);
#pragma unroll
    for (int mf = 0; mf < 4; mf++) {
#pragma unroll
        for (int nf = 0; nf < 4; nf++) {
            int row = bm + wm + mf * 16 + gid;
            int col = bn + wn + nf * 8 + 2 * tig;
            float v0 = acc[mf][nf][0], v1 = acc[mf][nf][1];
            float v2 = acc[mf][nf][2], v3 = acc[mf][nf][3];
            if (hb) {
                float bb0 = bias[col], bb1 = bias[col + 1];
                v0 = __fadd_rn(v0, bb0); v1 = __fadd_rn(v1, bb1);
                v2 = __fadd_rn(v2, bb0); v3 = __fadd_rn(v3, bb1);
            }
            *(float2*)&C[(size_t)row * N + col]       = make_float2(v0, v1);
            *(float2*)&C[(size_t)(row + 8) * N + col] = make_float2(v2, v3);
        }
    }
}

// ---------------- gating + exact k-winners (+ fused h split) ----------------
__global__ __launch_bounds__(256)
void gate_topk(const float* __restrict__ y, const float* __restrict__ dend,
               __nv_bfloat16* __restrict__ hh, __nv_bfloat16* __restrict__ hm,
               __nv_bfloat16* __restrict__ hl)
{
    __shared__ float     vals[HID];
    __shared__ unsigned  keys[HID];
    __shared__ int       hist[256];
    __shared__ unsigned  s_prefix;
    __shared__ int       s_remaining;

    const int b   = blockIdx.x;
    const int tid = threadIdx.x;
    const float* drow = dend + (size_t)b * HID * NSEG;
    const float* yrow = y    + (size_t)b * HID;

    for (int h = tid; h < HID; h += 256) {
        // 10 segment values, vectorized float2 loads (40B per unit, 8B aligned)
        const float2* d2 = (const float2*)(drow + (size_t)h * NSEG);
        float sv[NSEG];
#pragma unroll
        for (int q = 0; q < 5; q++) {
            float2 vv = d2[q];
            sv[2 * q] = vv.x; sv[2 * q + 1] = vv.y;
        }
        float best = 0.f, bestabs = -1.f;
#pragma unroll
        for (int s = 0; s < NSEG; s++) {
            float a = fabsf(sv[s]);
            if (a > bestabs) { bestabs = a; best = sv[s]; }  // first-occurrence argmax
        }
        float g = yrow[h] * (1.f / (1.f + expf(-best)));
        vals[h] = g;
        unsigned u = __float_as_uint(g);
        keys[h] = (u & 0x80000000u) ? ~u : (u | 0x80000000u);
    }
    if (tid == 0) { s_prefix = 0u; s_remaining = KWIN; }
    __syncthreads();

    for (int d = 3; d >= 0; d--) {
        hist[tid] = 0;
        __syncthreads();
        const unsigned pmask = (d == 3) ? 0u : (0xFFFFFFFFu << ((d + 1) * 8));
        const unsigned pref  = s_prefix;
        const int shift = d * 8;
        for (int h = tid; h < HID; h += 256) {
            unsigned kk = keys[h];
            if ((kk & pmask) == pref)
                atomicAdd(&hist[(kk >> shift) & 0xFF], 1);
        }
        __syncthreads();
        if (tid == 0) {
            int rem = s_remaining, cum = 0, bkt = 255;
            for (; bkt > 0; bkt--) {
                int c = hist[bkt];
                if (cum + c >= rem) break;
                cum += c;
            }
            s_remaining = rem - cum;
            s_prefix    = pref | ((unsigned)bkt << shift);
        }
        __syncthreads();
    }

    const unsigned kth = s_prefix;
    for (int h = tid; h < HID; h += 256) {
        float v = (keys[h] >= kth) ? vals[h] : 0.f;
        size_t o = (size_t)b * HID + h;
        __nv_bfloat16 hb = __float2bfloat16(v);
        float hf = __bfloat162float(hb);
        float r1 = v - hf;
        __nv_bfloat16 mb = __float2bfloat16(r1);
        float r2 = r1 - __bfloat162float(mb);
        hh[o] = hb; hm[o] = mb; hl[o] = __float2bfloat16(r2);
    }
}

// ---------------- launch -----------------------------------------------------
extern "C" void kernel_launch(void* const* d_in, const int* in_sizes, int n_in,
                              void* d_out, int out_size)
{
    (void)in_sizes; (void)n_in; (void)out_size;
    const float* x     = (const float*)d_in[0];
    const float* ctx   = (const float*)d_in[1];
    const float* w1    = (const float*)d_in[2];
    const float* b1    = (const float*)d_in[3];
    const float* seg1  = (const float*)d_in[4];
    const float* w2    = (const float*)d_in[5];
    const float* b2    = (const float*)d_in[6];
    const float* seg2  = (const float*)d_in[7];
    const float* w_out = (const float*)d_in[8];
    const float* b_out = (const float*)d_in[9];
    float* out = (float*)d_out;

    float *dendp, *yp;
    cudaGetSymbolAddress((void**)&dendp, g_dend);
    cudaGetSymbolAddress((void**)&yp,    g_y);
    __nv_bfloat16 *xs, *cs, *w1s, *s1s, *w2s, *s2s, *wos, *hs;
    cudaGetSymbolAddress((void**)&xs,  g_xs);
    cudaGetSymbolAddress((void**)&cs,  g_cs);
    cudaGetSymbolAddress((void**)&w1s, g_w1s);
    cudaGetSymbolAddress((void**)&s1s, g_s1s);
    cudaGetSymbolAddress((void**)&w2s, g_w2s);
    cudaGetSymbolAddress((void**)&s2s, g_s2s);
    cudaGetSymbolAddress((void**)&wos, g_wos);
    cudaGetSymbolAddress((void**)&hs,  g_hs);

    const size_t nx = (size_t)B_SZ * D_IN,  nc = (size_t)B_SZ * D_CTX;
    const size_t n1 = (size_t)HID * D_IN,   ns = (size_t)HID * NSEG * D_CTX;
    const size_t n2 = (size_t)HID * HID,    no = (size_t)D_OUT * HID;
    const size_t nh = (size_t)B_SZ * HID;

    cudaFuncSetAttribute(gemm_mma6, cudaFuncAttributeMaxDynamicSharedMemorySize, SMEM_B);

    split_kernel<<<1024, 256>>>(x,     xs,  xs + nx,  xs + 2*nx,  nx);
    split_kernel<<<1024, 256>>>(ctx,   cs,  cs + nc,  cs + 2*nc,  nc);
    split_kernel<<<1024, 256>>>(w1,    w1s, w1s + n1, w1s + 2*n1, n1);
    split_kernel<<<2048, 256>>>(seg1,  s1s, s1s + ns, s1s + 2*ns, ns);
    split_kernel<<<1024, 256>>>(w2,    w2s, w2s + n2, w2s + 2*n2, n2);
    split_kernel<<<2048, 256>>>(seg2,  s2s, s2s + ns, s2s + 2*ns, ns);
    split_kernel<<<1024, 256>>>(w_out, wos, wos + no, wos + 2*no, no);

    // layer 1
    gemm_mma6<<<dim3(HID / GT, B_SZ / GT), 256, SMEM_B>>>(
        xs, xs + nx, xs + 2*nx, w1s, w1s + n1, w1s + 2*n1, b1, yp, B_SZ, HID, D_IN);
    gemm_mma6<<<dim3(HID * NSEG / GT, B_SZ / GT), 256, SMEM_B>>>(
        cs, cs + nc, cs + 2*nc, s1s, s1s + ns, s1s + 2*ns, nullptr, dendp, B_SZ, HID * NSEG, D_CTX);
    gate_topk<<<B_SZ, 256>>>(yp, dendp, hs, hs + nh, hs + 2*nh);

    // layer 2
    gemm_mma6<<<dim3(HID / GT, B_SZ / GT), 256, SMEM_B>>>(
        hs, hs + nh, hs + 2*nh, w2s, w2s + n2, w2s + 2*n2, b2, yp, B_SZ, HID, HID);
    gemm_mma6<<<dim3(HID * NSEG / GT, B_SZ / GT), 256, SMEM_B>>>(
        cs, cs + nc, cs + 2*nc, s2s, s2s + ns, s2s + 2*ns, nullptr, dendp, B_SZ, HID * NSEG, D_CTX);
    gate_topk<<<B_SZ, 256>>>(yp, dendp, hs, hs + nh, hs + 2*nh);

    // output projection
    gemm_mma6<<<dim3(D_OUT / GT, B_SZ / GT), 256, SMEM_B>>>(
        hs, hs + nh, hs + 2*nh, wos, wos + no, wos + 2*no, b_out, out, B_SZ, D_OUT, HID);
}